// round 3
// baseline (speedup 1.0000x reference)
#include <cuda_runtime.h>
#include <math.h>
#include <stdint.h>

typedef unsigned long long ull;

// Problem constants
#define NB 32
#define C 128
#define HW 4096
#define K 64
#define KE 56
#define TP 128
#define NTILES (HW / TP)   // 32
#define NTHR 512

#define XS_STRIDE 130      // 130 % 32 == 2 -> 2-phase (min) wide LDS.64 column access
#define WT_STRIDE 68       // 68*4 % 16 == 0 -> 16B-aligned rows for bcast LDS.128
#define LS_STRIDE 132      // 132*4 % 16 == 0 -> 16B-aligned rows for bcast LDS.128

// Dynamic smem layout (floats)
#define XS_OFF 0
#define XS_SZ  (C * XS_STRIDE)          // 16640
#define WT_OFF (XS_OFF + XS_SZ)
#define WT_SZ  (C * WT_STRIDE)          // 8704
#define LS_OFF (WT_OFF + WT_SZ)
#define LS_SZ  (K * LS_STRIDE)          // 8448
#define SMEM_FLOATS (LS_OFF + LS_SZ)    // 33792
#define SMEM_BYTES  (SMEM_FLOATS * 4)   // 135168

// Per-(n,tile) partial scratch -- unique slots, plain stores, no atomics, no zeroing
__device__ float g_part[NB * NTILES * KE * C];   // 29.36 MB
__device__ float g_asum_part[NB * NTILES * KE];  // 229 KB

// ---- f32x2 helpers ----
__device__ __forceinline__ ull ffma2(ull a, ull b, ull c) {
    ull d;
    asm("fma.rn.f32x2 %0, %1, %2, %3;" : "=l"(d) : "l"(a), "l"(b), "l"(c));
    return d;
}
__device__ __forceinline__ ull dup2(float v) {
    ull d;
    unsigned u = __float_as_uint(v);
    asm("mov.b64 %0, {%1, %1};" : "=l"(d) : "r"(u));
    return d;
}
__device__ __forceinline__ void unpack2(ull v, float& lo, float& hi) {
    unsigned a, b;
    asm("mov.b64 {%0, %1}, %2;" : "=r"(a), "=r"(b) : "l"(v));
    lo = __uint_as_float(a);
    hi = __uint_as_float(b);
}
__device__ __forceinline__ float f2sum(ull v) {
    float lo, hi;
    unpack2(v, lo, hi);
    return lo + hi;
}

__global__ __launch_bounds__(NTHR, 1)
void netvlad_main(const float* __restrict__ x,
                  const float* __restrict__ conv_w,
                  const float* __restrict__ conv_b) {
    extern __shared__ float sm[];
    float* xs = sm + XS_OFF;   // [C][XS_STRIDE]  raw x tile
    float* wt = sm + WT_OFF;   // [C][WT_STRIDE]  W^T (k contiguous)
    float* ls = sm + LS_OFF;   // [K][LS_STRIDE]  logits -> assignments

    __shared__ float red4[4 * TP];
    __shared__ float rn[TP];
    __shared__ float sinv[TP];
    __shared__ float bs[K];

    const int n    = blockIdx.x;
    const int tile = blockIdx.y;
    const int tid  = threadIdx.x;
    const int lane = tid & 31;
    const int w    = tid >> 5;

    // ---- Load W transposed: wt[c][k] = conv_w[k][c]; bias ----
    for (int idx = tid; idx < K * C; idx += NTHR) {
        int k = idx >> 7, c = idx & 127;
        wt[c * WT_STRIDE + k] = __ldg(conv_w + idx);
    }
    if (tid < K) bs[tid] = conv_b[tid];

    // ---- Load raw x tile: GMEM [c][p] -> xs[c][p] ----
    const float* xt = x + (size_t)n * C * HW + tile * TP;
    for (int idx = tid; idx < C * (TP / 4); idx += NTHR) {
        int c = idx >> 5, p4 = idx & 31;
        float4 v = __ldg((const float4*)(xt + (size_t)c * HW) + p4);
        float* dst = xs + c * XS_STRIDE + p4 * 4;
        *(ull*)(dst)     = *(ull*)&v.x;
        *(ull*)(dst + 2) = *(ull*)&v.z;
    }
    __syncthreads();

    // ---- Sum of squares per pixel -> rn (4 c-segments x 128 p) ----
    {
        const int p = tid & 127, seg = tid >> 7;
        float ss = 0.0f;
        const int c0 = seg * 32;
#pragma unroll 8
        for (int i = 0; i < 32; ++i) {
            float v = xs[(c0 + i) * XS_STRIDE + p];
            ss += v * v;
        }
        red4[seg * TP + p] = ss;
        __syncthreads();
        if (tid < TP) {
            float tot = red4[tid] + red4[TP + tid] + red4[2 * TP + tid] + red4[3 * TP + tid];
            rn[tid] = 1.0f / fmaxf(sqrtf(tot), 1e-12f);
        }
        __syncthreads();
    }

    // ---- GEMM1: logits (k-paired f32x2). warp -> (8 k, 64 p) ----
    {
        const int kb = (w >> 1) * 8;
        const int pb = (w & 1) * 64 + lane;
        ull acc[4][2];
#pragma unroll
        for (int i = 0; i < 4; ++i) { acc[i][0] = 0ull; acc[i][1] = 0ull; }

#pragma unroll 2
        for (int c = 0; c < C; ++c) {
            const float* wr = wt + c * WT_STRIDE + kb;
            ulonglong2 wv0 = *(const ulonglong2*)(wr);      // k pairs (kb,kb+1),(kb+2,kb+3)
            ulonglong2 wv1 = *(const ulonglong2*)(wr + 4);  // (kb+4,kb+5),(kb+6,kb+7)
            ull xd0 = dup2(xs[c * XS_STRIDE + pb]);
            ull xd1 = dup2(xs[c * XS_STRIDE + pb + 32]);
            acc[0][0] = ffma2(wv0.x, xd0, acc[0][0]);
            acc[1][0] = ffma2(wv0.y, xd0, acc[1][0]);
            acc[2][0] = ffma2(wv1.x, xd0, acc[2][0]);
            acc[3][0] = ffma2(wv1.y, xd0, acc[3][0]);
            acc[0][1] = ffma2(wv0.x, xd1, acc[0][1]);
            acc[1][1] = ffma2(wv0.y, xd1, acc[1][1]);
            acc[2][1] = ffma2(wv1.x, xd1, acc[2][1]);
            acc[3][1] = ffma2(wv1.y, xd1, acc[3][1]);
        }
        // epilogue: ls[k][p] = dot * rn[p] + b[k]
        float rn0 = rn[pb], rn1 = rn[pb + 32];
#pragma unroll
        for (int kp = 0; kp < 4; ++kp) {
            int k0 = kb + 2 * kp;
            float b0 = bs[k0], b1 = bs[k0 + 1];
            float lo, hi;
            unpack2(acc[kp][0], lo, hi);
            ls[k0 * LS_STRIDE + pb]       = lo * rn0 + b0;
            ls[(k0 + 1) * LS_STRIDE + pb] = hi * rn0 + b1;
            unpack2(acc[kp][1], lo, hi);
            ls[k0 * LS_STRIDE + pb + 32]       = lo * rn1 + b0;
            ls[(k0 + 1) * LS_STRIDE + pb + 32] = hi * rn1 + b1;
        }
    }
    __syncthreads();

    // ---- Softmax over k per pixel (4 k-quarters x 128 p) ----
    {
        const int p = tid & 127, q = tid >> 7;
        const int k0 = q * 16;
        float m = -1e30f;
#pragma unroll 8
        for (int i = 0; i < 16; ++i) m = fmaxf(m, ls[(k0 + i) * LS_STRIDE + p]);
        red4[q * TP + p] = m;
        __syncthreads();
        float M = fmaxf(fmaxf(red4[p], red4[TP + p]), fmaxf(red4[2 * TP + p], red4[3 * TP + p]));
        __syncthreads();
        float s = 0.0f;
#pragma unroll 8
        for (int i = 0; i < 16; ++i) {
            float e = __expf(ls[(k0 + i) * LS_STRIDE + p] - M);
            ls[(k0 + i) * LS_STRIDE + p] = e;
            s += e;
        }
        red4[q * TP + p] = s;
        __syncthreads();
        if (tid < TP)
            sinv[tid] = 1.0f / (red4[tid] + red4[TP + tid] + red4[2 * TP + tid] + red4[3 * TP + tid]);
        __syncthreads();
    }

    // ---- asum (a = e*sinv) + fold rn into assignments (a' = a*rn); 14 warps x 4 k ----
    if (w < 14) {
        const int kb = w * 4;
        float si[4], sir[4];
#pragma unroll
        for (int j = 0; j < 4; ++j) {
            int p = lane + 32 * j;
            si[j] = sinv[p];
            sir[j] = si[j] * rn[p];
        }
#pragma unroll
        for (int i = 0; i < 4; ++i) {
            float sv = 0.0f;
#pragma unroll
            for (int j = 0; j < 4; ++j) {
                float* ap = ls + (kb + i) * LS_STRIDE + lane + 32 * j;
                float e = *ap;
                sv += e * si[j];
                *ap = e * sir[j];
            }
#pragma unroll
            for (int off = 16; off; off >>= 1) sv += __shfl_down_sync(0xffffffffu, sv, off);
            if (lane == 0)
                g_asum_part[(n * NTILES + tile) * KE + kb + i] = sv;
        }
    }
    __syncthreads();

    // ---- GEMM2: vlad partial (p-paired f32x2). warp -> (7 k, 64 c) ----
    {
        const int kb = (w >> 1) * 7;
        const int cb = (w & 1) * 64 + lane;
        ull vacc[7][2];
#pragma unroll
        for (int i = 0; i < 7; ++i) { vacc[i][0] = 0ull; vacc[i][1] = 0ull; }

        const float* ap0 = ls + kb * LS_STRIDE;
        const float* xv0 = xs + cb * XS_STRIDE;
        const float* xv1 = xs + (cb + 32) * XS_STRIDE;
#pragma unroll 2
        for (int p4 = 0; p4 < TP / 4; ++p4) {
            ulonglong2 a2[7];
#pragma unroll
            for (int i = 0; i < 7; ++i)
                a2[i] = *(const ulonglong2*)(ap0 + i * LS_STRIDE + 4 * p4);  // bcast .128
            ull x00 = *(const ull*)(xv0 + 4 * p4);
            ull x01 = *(const ull*)(xv0 + 4 * p4 + 2);
            ull x10 = *(const ull*)(xv1 + 4 * p4);
            ull x11 = *(const ull*)(xv1 + 4 * p4 + 2);
#pragma unroll
            for (int i = 0; i < 7; ++i) {
                vacc[i][0] = ffma2(a2[i].x, x00, vacc[i][0]);
                vacc[i][0] = ffma2(a2[i].y, x01, vacc[i][0]);
                vacc[i][1] = ffma2(a2[i].x, x10, vacc[i][1]);
                vacc[i][1] = ffma2(a2[i].y, x11, vacc[i][1]);
            }
        }
        // flush partials: plain stores to unique slot
        float* gp = g_part + ((size_t)(n * NTILES + tile) * KE + kb) * C;
#pragma unroll
        for (int i = 0; i < 7; ++i) {
            gp[i * C + cb]      = f2sum(vacc[i][0]);
            gp[i * C + cb + 32] = f2sum(vacc[i][1]);
        }
    }
}

__global__ __launch_bounds__(256)
void netvlad_finalize(const float* __restrict__ centroids, float* __restrict__ out) {
    __shared__ float ys[KE * C];       // 28 KB
    __shared__ float colss[8 * C];     // 4 KB
    __shared__ float colinv[C];
    __shared__ float asl[KE];
    __shared__ float red[8];
    __shared__ float s_inv2;

    const int n = blockIdx.x;
    const int tid = threadIdx.x;

    // asum totals over 32 tiles
    if (tid < KE) {
        float s = 0.0f;
        const float* ap = g_asum_part + (size_t)n * NTILES * KE + tid;
#pragma unroll 8
        for (int t = 0; t < NTILES; ++t) s += ap[t * KE];
        asl[tid] = s;
    }

    // vlad totals over 32 tiles (7 float4 elements per thread)
    float4 s[7];
#pragma unroll
    for (int r = 0; r < 7; ++r) {
        int e4 = tid + r * 256;
        const float* bp = g_part + (size_t)n * NTILES * KE * C + e4 * 4;
        float4 acc = make_float4(0.f, 0.f, 0.f, 0.f);
#pragma unroll 8
        for (int t = 0; t < NTILES; ++t) {
            float4 v = *(const float4*)(bp + (size_t)t * KE * C);
            acc.x += v.x; acc.y += v.y; acc.z += v.z; acc.w += v.w;
        }
        s[r] = acc;
    }
    __syncthreads();

    // subtract a_sum * centroid, store ys, accumulate per-column ssq
    const int cg = (tid & 31) * 4;  // fixed 4-c group per thread
    float4 ss4 = make_float4(0.f, 0.f, 0.f, 0.f);
#pragma unroll
    for (int r = 0; r < 7; ++r) {
        int e4 = tid + r * 256;
        int k = e4 >> 5;
        float a = asl[k];
        float4 ce = *(const float4*)(centroids + k * C + cg);
        float4 y;
        y.x = s[r].x - a * ce.x;
        y.y = s[r].y - a * ce.y;
        y.z = s[r].z - a * ce.z;
        y.w = s[r].w - a * ce.w;
        *(float4*)(ys + k * C + cg) = y;
        ss4.x += y.x * y.x; ss4.y += y.y * y.y;
        ss4.z += y.z * y.z; ss4.w += y.w * y.w;
    }
    *(float4*)(colss + (tid >> 5) * C + cg) = ss4;
    __syncthreads();

    float gs = 0.0f;
    if (tid < C) {
        float cs = 0.0f;
#pragma unroll
        for (int g = 0; g < 8; ++g) cs += colss[g * C + tid];
        float i1 = 1.0f / fmaxf(sqrtf(cs), 1e-12f);
        gs = cs * i1 * i1;
        colinv[tid] = i1;
    }
    __syncthreads();
#pragma unroll
    for (int off = 16; off; off >>= 1) gs += __shfl_down_sync(0xffffffffu, gs, off);
    if ((tid & 31) == 0) red[tid >> 5] = gs;
    __syncthreads();
    if (tid == 0) {
        float t = red[0] + red[1] + red[2] + red[3];
        s_inv2 = 1.0f / fmaxf(sqrtf(t), 1e-12f);
    }
    __syncthreads();
    const float inv2 = s_inv2;
    float* op = out + (size_t)n * KE * C;
    for (int idx = tid; idx < KE * C; idx += 256)
        op[idx] = ys[idx] * colinv[idx & 127] * inv2;
}

extern "C" void kernel_launch(void* const* d_in, const int* in_sizes, int n_in,
                              void* d_out, int out_size) {
    const float* x      = (const float*)d_in[0];
    const float* conv_w = (const float*)d_in[1];
    const float* conv_b = (const float*)d_in[2];
    const float* cen    = (const float*)d_in[3];
    float* out = (float*)d_out;

    cudaFuncSetAttribute(netvlad_main, cudaFuncAttributeMaxDynamicSharedMemorySize, SMEM_BYTES);

    netvlad_main<<<dim3(NB, NTILES), NTHR, SMEM_BYTES>>>(x, conv_w, conv_b);
    netvlad_finalize<<<NB, 256>>>(cen, out);
}